// round 3
// baseline (speedup 1.0000x reference)
#include <cuda_runtime.h>
#include <cstdint>

#define R  5
#define NU 4096
#define NV 4096
#define DD 256
#define HH 64
#define BB 4096

// ---------------- scratch (no allocations allowed) ----------------
__device__ float g_cinv[R * NU];     // rowsum (sum over m) -> rsqrt -> c_inv (per n)
__device__ float g_rinv[R * NV];     // colsum (sum over n) -> rsqrt -> r_inv (per m)
__device__ float g_cwu[R * DD * HH]; // cumsum u_weight
__device__ float g_cwv[R * DD * HH]; // cumsum v_weight
__device__ float g_tu2[R * NU * HH]; // u_feat @ cwu   (UNscaled)
__device__ float g_tv2[R * NV * HH]; // v_feat @ cwv   (UNscaled)
__device__ float g_yu[NU * HH];      // y_u[n][h]
__device__ float g_yvT[HH * NV];     // y_v transposed [h][m]

// ---------------- tf32 mma helper ----------------
__device__ __forceinline__ void mma_tf32(float* d, const uint32_t* a, const uint32_t* b) {
    asm volatile(
        "mma.sync.aligned.m16n8k8.row.col.f32.tf32.tf32.f32 "
        "{%0,%1,%2,%3},{%4,%5,%6,%7},{%8,%9},{%0,%1,%2,%3};"
        : "+f"(d[0]), "+f"(d[1]), "+f"(d[2]), "+f"(d[3])
        : "r"(a[0]), "r"(a[1]), "r"(a[2]), "r"(a[3]),
          "r"(b[0]), "r"(b[1]));
}

// ---------------- K0: zero accumulators ----------------
__global__ void zero_kernel() {
    int i = blockIdx.x * 256 + threadIdx.x;
    if (i < R * NU) g_cinv[i] = 0.f;
    if (i < R * NV) g_rinv[i] = 0.f;
    if (i < NU * HH) g_yu[i] = 0.f;
    if (i < HH * NV) g_yvT[i] = 0.f;
}

// ---------------- K1: row & col sums of support ----------------
__global__ __launch_bounds__(256) void sums_kernel(const float* __restrict__ support) {
    int r = blockIdx.y;
    int nb = blockIdx.x;
    int t = threadIdx.x;
    int warp = t >> 5, lane = t & 31;
    const float* base = support + (size_t)r * NU * NV + (size_t)nb * 64 * NV;

    float colacc[16];
#pragma unroll
    for (int i = 0; i < 16; ++i) colacc[i] = 0.f;

    __shared__ float rowpart[64 * 8];

    for (int row = 0; row < 64; ++row) {
        const float4* p = (const float4*)(base + (size_t)row * NV);
        float rs = 0.f;
#pragma unroll
        for (int j = 0; j < 4; ++j) {
            float4 v = p[t + j * 256];
            colacc[j * 4 + 0] += v.x;
            colacc[j * 4 + 1] += v.y;
            colacc[j * 4 + 2] += v.z;
            colacc[j * 4 + 3] += v.w;
            rs += (v.x + v.y) + (v.z + v.w);
        }
#pragma unroll
        for (int o = 16; o; o >>= 1) rs += __shfl_xor_sync(0xffffffffu, rs, o);
        if (lane == 0) rowpart[row * 8 + warp] = rs;
    }
    __syncthreads();
    if (t < 64) {
        float s = 0.f;
#pragma unroll
        for (int w = 0; w < 8; ++w) s += rowpart[t * 8 + w];
        g_cinv[r * NU + nb * 64 + t] = s;
    }
#pragma unroll
    for (int j = 0; j < 4; ++j)
#pragma unroll
        for (int c = 0; c < 4; ++c)
            atomicAdd(&g_rinv[r * NV + 4 * t + 1024 * j + c], colacc[j * 4 + c]);
}

// ---------------- K2: sums -> rsqrt scalings ----------------
__global__ void inv_kernel() {
    int i = blockIdx.x * 256 + threadIdx.x;
    if (i < R * NU) {
        float v = g_cinv[i];
        g_cinv[i] = (v > 0.f) ? rsqrtf(v) : 0.f;
    }
    if (i < R * NV) {
        float v = g_rinv[i];
        g_rinv[i] = (v > 0.f) ? rsqrtf(v) : 0.f;
    }
}

// ---------------- K3: cumsum of weights over r ----------------
__global__ void cumsum_kernel(const float* __restrict__ uw, const float* __restrict__ vw) {
    int i = blockIdx.x * 256 + threadIdx.x;
    int which = blockIdx.y;
    const float* w = which ? vw : uw;
    float* cw = which ? g_cwv : g_cwu;
    float a = 0.f;
#pragma unroll
    for (int r = 0; r < R; ++r) {
        a += w[r * DD * HH + i];
        cw[r * DD * HH + i] = a;
    }
}

// ---------------- K4: tmp GEMMs (unscaled now) ----------------
__global__ __launch_bounds__(256) void tmp_kernel(const float* __restrict__ u_feat,
                                                  const float* __restrict__ v_feat) {
    __shared__ float sA[128 * 36];
    __shared__ float sB[32 * 68];
    int which = blockIdx.z;
    int r = blockIdx.y;
    int n0 = blockIdx.x * 128;
    const float* feat = which ? v_feat : u_feat;
    const float* cw = which ? g_cwv : g_cwu;
    float* out = which ? g_tv2 : g_tu2;

    int t = threadIdx.x;
    int tx = t & 15, ty = t >> 4;

    float acc[8][4];
#pragma unroll
    for (int j = 0; j < 8; ++j)
#pragma unroll
        for (int c = 0; c < 4; ++c) acc[j][c] = 0.f;

    for (int kc = 0; kc < DD / 32; ++kc) {
        int k0 = kc * 32;
#pragma unroll
        for (int i = 0; i < 4; ++i) {
            int q = t + 256 * i;
            int row = q >> 3, c4 = q & 7;
            float4 v = *(const float4*)(feat + (size_t)(n0 + row) * DD + k0 + c4 * 4);
            *(float4*)&sA[row * 36 + c4 * 4] = v;
        }
#pragma unroll
        for (int i = 0; i < 2; ++i) {
            int q = t + 256 * i;
            int row = q >> 4, c4 = q & 15;
            float4 v = *(const float4*)(cw + (size_t)r * DD * HH + (size_t)(k0 + row) * HH + c4 * 4);
            *(float4*)&sB[row * 68 + c4 * 4] = v;
        }
        __syncthreads();
#pragma unroll 4
        for (int kk = 0; kk < 32; ++kk) {
            float4 bv = *(float4*)&sB[kk * 68 + tx * 4];
#pragma unroll
            for (int j = 0; j < 8; ++j) {
                float a = sA[(ty * 8 + j) * 36 + kk];
                acc[j][0] = fmaf(a, bv.x, acc[j][0]);
                acc[j][1] = fmaf(a, bv.y, acc[j][1]);
                acc[j][2] = fmaf(a, bv.z, acc[j][2]);
                acc[j][3] = fmaf(a, bv.w, acc[j][3]);
            }
        }
        __syncthreads();
    }
#pragma unroll
    for (int j = 0; j < 8; ++j) {
        int n = n0 + ty * 8 + j;
#pragma unroll
        for (int c = 0; c < 4; ++c)
            out[((size_t)r * NU + n) * HH + tx * 4 + c] = acc[j][c];
    }
}

// ---------------- K5: FUSED contraction ----------------
// CTA tile: n in [n0, n0+128), m in [m0, m0+128). Loops r=0..4 internally.
// smem tile S = c_inv[r,n] * sup[r,n,m] * r_inv[r,m]  (fully normalized),
// used as A for yu (k=m) and as B for yv (k=n).
//   yu[n,h] += S @ tv2[r]   (tv2 tile sV [128m x 64h])
//   yv[m,h] += S^T @ tu2[r] computed as D[64h x 128m] with A = tu2^T (sU [128n x 64h])
__global__ __launch_bounds__(256, 1) void fused_kernel(const float* __restrict__ support) {
    extern __shared__ float smem[];
    float* sS = smem;                 // 128*36 = 4608 floats
    float* sU = smem + 4608;          // 128*72 = 9216 floats
    float* sV = sU + 9216;            // 9216 floats
    float* sC = sV + 9216;            // 128
    float* sRi = sC + 128;            // 128

    int t = threadIdx.x;
    int lane = t & 31, warp = t >> 5;
    int g = lane >> 2, tg = lane & 3;
    int m0 = blockIdx.x * 128;
    int n0 = blockIdx.y * 128;

    // yu warp layout: wyU (0..3) 32-n band, wxU (0..1) 32-h band
    int wyU = warp >> 1, wxU = warp & 1;
    // yv warp layout: wyV (0..3) 16-h band, wxV (0..1) 16-m sub-band within 32-m chunk
    int wyV = warp >> 1, wxV = warp & 1;

    float accU[2][4][4];
    float accV[4][2][4];
#pragma unroll
    for (int a = 0; a < 2; ++a)
#pragma unroll
        for (int b = 0; b < 4; ++b)
#pragma unroll
            for (int c = 0; c < 4; ++c) accU[a][b][c] = 0.f;
#pragma unroll
    for (int a = 0; a < 4; ++a)
#pragma unroll
        for (int b = 0; b < 2; ++b)
#pragma unroll
            for (int c = 0; c < 4; ++c) accV[a][b][c] = 0.f;

    // prefetch support chunk for step 0 (r=0, mc=0)
    float4 pf[4];
#pragma unroll
    for (int i = 0; i < 4; ++i) {
        int q = t + 256 * i;
        int row = q >> 3, c4 = q & 7;
        pf[i] = *(const float4*)(support + ((size_t)(n0 + row)) * NV + m0 + c4 * 4);
    }

    for (int r = 0; r < R; ++r) {
        // load per-r operand tiles + scales (previous compute finished at loop-end sync)
#pragma unroll
        for (int i = 0; i < 8; ++i) {
            int q = t + 256 * i;
            int row = q >> 4, c4 = q & 15;
            float4 uu = *(const float4*)(g_tu2 + ((size_t)(r * NU + n0 + row)) * HH + c4 * 4);
            *(float4*)&sU[row * 72 + c4 * 4] = uu;
            float4 vv = *(const float4*)(g_tv2 + ((size_t)(r * NV + m0 + row)) * HH + c4 * 4);
            *(float4*)&sV[row * 72 + c4 * 4] = vv;
        }
        if (t < 32) {
            *(float4*)&sC[t * 4] = *(const float4*)(g_cinv + r * NU + n0 + t * 4);
        } else if (t < 64) {
            int tt = t - 32;
            *(float4*)&sRi[tt * 4] = *(const float4*)(g_rinv + r * NV + m0 + tt * 4);
        }
        __syncthreads();

#pragma unroll
        for (int mc = 0; mc < 4; ++mc) {
            // store normalized support chunk to smem
#pragma unroll
            for (int i = 0; i < 4; ++i) {
                int q = t + 256 * i;
                int row = q >> 3, c4 = q & 7;
                float cr = sC[row];
                float4 ri = *(float4*)&sRi[mc * 32 + c4 * 4];
                float4 v = pf[i];
                v.x *= cr * ri.x;
                v.y *= cr * ri.y;
                v.z *= cr * ri.z;
                v.w *= cr * ri.w;
                *(float4*)&sS[row * 36 + c4 * 4] = v;
            }
            __syncthreads();

            // prefetch next chunk (clamped on last step; redundant L2 hit)
            {
                int s2 = r * 4 + mc + 1;
                if (s2 > R * 4 - 1) s2 = R * 4 - 1;
                int rn = s2 >> 2, mn = s2 & 3;
#pragma unroll
                for (int i = 0; i < 4; ++i) {
                    int q = t + 256 * i;
                    int row = q >> 3, c4 = q & 7;
                    pf[i] = *(const float4*)(support + ((size_t)rn * NU + n0 + row) * NV +
                                             m0 + mn * 32 + c4 * 4);
                }
            }

            // ---- yu: D[128n x 64h], A = sS [n][k=m], B = sV [k=m][h], k=32 ----
#pragma unroll
            for (int ks = 0; ks < 4; ++ks) {
                uint32_t b[4][2];
#pragma unroll
                for (int ct = 0; ct < 4; ++ct) {
                    int cb = wxU * 32 + ct * 8;
                    b[ct][0] = __float_as_uint(sV[(mc * 32 + ks * 8 + tg) * 72 + cb + g]);
                    b[ct][1] = __float_as_uint(sV[(mc * 32 + ks * 8 + tg + 4) * 72 + cb + g]);
                }
#pragma unroll
                for (int rt = 0; rt < 2; ++rt) {
                    int rb = wyU * 32 + rt * 16;
                    uint32_t a[4];
                    a[0] = __float_as_uint(sS[(rb + g) * 36 + ks * 8 + tg]);
                    a[1] = __float_as_uint(sS[(rb + g + 8) * 36 + ks * 8 + tg]);
                    a[2] = __float_as_uint(sS[(rb + g) * 36 + ks * 8 + tg + 4]);
                    a[3] = __float_as_uint(sS[(rb + g + 8) * 36 + ks * 8 + tg + 4]);
#pragma unroll
                    for (int ct = 0; ct < 4; ++ct) mma_tf32(accU[rt][ct], a, b[ct]);
                }
            }

            // ---- yv chunk: D[16h x 16m] per warp, A = sU^T [h][k=n], B = sS [k=n][m], k=128 ----
            {
                int hb = wyV * 16;
                int mbase = wxV * 16;
#pragma unroll
                for (int ks = 0; ks < 16; ++ks) {
                    uint32_t a[4];
                    a[0] = __float_as_uint(sU[(ks * 8 + tg) * 72 + hb + g]);
                    a[1] = __float_as_uint(sU[(ks * 8 + tg) * 72 + hb + g + 8]);
                    a[2] = __float_as_uint(sU[(ks * 8 + tg + 4) * 72 + hb + g]);
                    a[3] = __float_as_uint(sU[(ks * 8 + tg + 4) * 72 + hb + g + 8]);
#pragma unroll
                    for (int ct = 0; ct < 2; ++ct) {
                        int mb = mbase + ct * 8;
                        uint32_t b[2];
                        b[0] = __float_as_uint(sS[(ks * 8 + tg) * 36 + mb + g]);
                        b[1] = __float_as_uint(sS[(ks * 8 + tg + 4) * 36 + mb + g]);
                        mma_tf32(accV[mc][ct], a, b);
                    }
                }
            }
            __syncthreads();
        }
    }

    // ---- epilogue: atomic accumulation over tile grid ----
#pragma unroll
    for (int rt = 0; rt < 2; ++rt) {
        int n1 = n0 + wyU * 32 + rt * 16 + g;
        int n2 = n1 + 8;
#pragma unroll
        for (int ct = 0; ct < 4; ++ct) {
            int h = wxU * 32 + ct * 8 + tg * 2;
            atomicAdd(&g_yu[n1 * HH + h], accU[rt][ct][0]);
            atomicAdd(&g_yu[n1 * HH + h + 1], accU[rt][ct][1]);
            atomicAdd(&g_yu[n2 * HH + h], accU[rt][ct][2]);
            atomicAdd(&g_yu[n2 * HH + h + 1], accU[rt][ct][3]);
        }
    }
#pragma unroll
    for (int mc = 0; mc < 4; ++mc) {
        int h1 = wyV * 16 + g;
        int h2 = h1 + 8;
#pragma unroll
        for (int ct = 0; ct < 2; ++ct) {
            int m = m0 + mc * 32 + wxV * 16 + ct * 8 + tg * 2;
            atomicAdd(&g_yvT[h1 * NV + m], accV[mc][ct][0]);
            atomicAdd(&g_yvT[h1 * NV + m + 1], accV[mc][ct][1]);
            atomicAdd(&g_yvT[h2 * NV + m], accV[mc][ct][2]);
            atomicAdd(&g_yvT[h2 * NV + m + 1], accV[mc][ct][3]);
        }
    }
}

// ---------------- K7: gather + bias + relu ----------------
__global__ void gather_kernel(const int* __restrict__ u, const int* __restrict__ v,
                              const float* __restrict__ bias, float* __restrict__ out) {
    int idx = blockIdx.x * 256 + threadIdx.x;
    int b = idx >> 6, h = idx & 63;
    float bi = bias[h];
    float zu = g_yu[u[b] * HH + h] + bi;
    float zv = g_yvT[h * NV + v[b]] + bi;
    out[idx] = fmaxf(zu, 0.f);
    out[BB * HH + idx] = fmaxf(zv, 0.f);
}

// ---------------- launcher ----------------
extern "C" void kernel_launch(void* const* d_in, const int* in_sizes, int n_in,
                              void* d_out, int out_size) {
    const float* u_feat = (const float*)d_in[0];
    const float* v_feat = (const float*)d_in[1];
    const int* u = (const int*)d_in[2];
    const int* v = (const int*)d_in[3];
    const float* support = (const float*)d_in[4];
    const float* u_weight = (const float*)d_in[5];
    const float* v_weight = (const float*)d_in[6];
    const float* u_bias = (const float*)d_in[7];
    float* out = (float*)d_out;

    const int fused_smem = (4608 + 9216 + 9216 + 128 + 128) * 4;  // 93184 bytes
    cudaFuncSetAttribute(fused_kernel, cudaFuncAttributeMaxDynamicSharedMemorySize, fused_smem);

    zero_kernel<<<(NU * HH + 255) / 256, 256>>>();
    sums_kernel<<<dim3(64, R), 256>>>(support);
    inv_kernel<<<(R * NU + 255) / 256, 256>>>();
    cumsum_kernel<<<dim3(DD * HH / 256, 2), 256>>>(u_weight, v_weight);
    tmp_kernel<<<dim3(32, R, 2), 256>>>(u_feat, v_feat);
    fused_kernel<<<dim3(32, 32), 256, fused_smem>>>(support);
    gather_kernel<<<BB * HH / 256, 256>>>(u, v, u_bias, out);
}